// round 1
// baseline (speedup 1.0000x reference)
#include <cuda_runtime.h>
#include <math.h>

#define NN 1024
#define HH 256
#define D0 71
#define BB 16
#define PP 523776   // NN*(NN-1)/2

// per-batch decision constant c = exp(l1 - l0)
__device__ float g_c[BB];

struct Ptrs { const float* p[30]; };

__device__ __forceinline__ float bred(float v, float* red) {
    #pragma unroll
    for (int o = 16; o > 0; o >>= 1) v += __shfl_down_sync(0xffffffffu, v, o);
    int lane = threadIdx.x & 31, w = threadIdx.x >> 5;
    if (lane == 0) red[w] = v;
    __syncthreads();
    if (w == 0) {
        float s = (lane < 8) ? red[lane] : 0.0f;
        #pragma unroll
        for (int o = 4; o > 0; o >>= 1) s += __shfl_down_sync(0xffffffffu, s, o);
        if (lane == 0) red[0] = s;
    }
    __syncthreads();
    float s = red[0];
    __syncthreads();
    return s;
}

__device__ __forceinline__ float geluf(float x) {
    return 0.5f * x * (1.0f + erff(x * 0.70710678118654752440f));
}

// One block per batch, 256 threads. Computes g_c[b] = exp(l1 - l0).
__global__ void __launch_bounds__(256) logits_kernel(Ptrs P) {
    const float* x     = P.p[0];
    const float* stats = P.p[1];
    const float* ln0_g = P.p[3];  const float* ln0_b = P.p[4];
    const float* r1lg  = P.p[5];  const float* r1lb  = P.p[6];
    const float* r1w1  = P.p[7];  const float* r1b1  = P.p[8];
    const float* r1w2  = P.p[9];  const float* r1b2  = P.p[10];
    const float* r1wp  = P.p[11]; const float* r1bp  = P.p[12];
    const float* r2lg  = P.p[13]; const float* r2lb  = P.p[14];
    const float* r2w1  = P.p[15]; const float* r2b1  = P.p[16];
    const float* r2w2  = P.p[17]; const float* r2b2  = P.p[18];
    const float* alg   = P.p[19]; const float* alb   = P.p[20];
    const float* awin  = P.p[21]; const float* abin  = P.p[22];
    const float* awout = P.p[23]; const float* about_= P.p[24];
    const float* ow    = P.p[25]; const float* ob    = P.p[26];
    const float* fw    = P.p[27]; const float* fb    = P.p[28];

    int b = blockIdx.x, tid = threadIdx.x;
    __shared__ float z[D0], a[HH], t[HH], h[HH], red[32], mv[2];

    if (tid < 64)       z[tid] = x[b * 64 + tid];
    else if (tid < D0)  z[tid] = stats[b * 7 + tid - 64];
    __syncthreads();

    // ln0 over 71 dims (serial stats on thread 0 — 71 elems, negligible)
    if (tid == 0) {
        float s = 0.f; for (int k = 0; k < D0; k++) s += z[k];
        float m = s / (float)D0, vv = 0.f;
        for (int k = 0; k < D0; k++) { float d = z[k] - m; vv += d * d; }
        vv /= (float)D0;
        mv[0] = m; mv[1] = 1.0f / sqrtf(vv + 1e-5f);
    }
    __syncthreads();
    if (tid < D0) z[tid] = (z[tid] - mv[0]) * mv[1] * ln0_g[tid] + ln0_b[tid];
    __syncthreads();

    // ---- residual block 1 (D0 -> H, with projection) ----
    if (tid == 0) {
        float s = 0.f; for (int k = 0; k < D0; k++) s += z[k];
        float m = s / (float)D0, vv = 0.f;
        for (int k = 0; k < D0; k++) { float d = z[k] - m; vv += d * d; }
        vv /= (float)D0;
        mv[0] = m; mv[1] = 1.0f / sqrtf(vv + 1e-5f);
    }
    __syncthreads();
    if (tid < D0) a[tid] = (z[tid] - mv[0]) * mv[1] * r1lg[tid] + r1lb[tid];
    __syncthreads();
    {
        float acc = r1b1[tid];
        #pragma unroll 8
        for (int k = 0; k < D0; k++) acc += __ldg(&r1w1[tid * D0 + k]) * a[k];
        t[tid] = geluf(acc);
    }
    __syncthreads();
    {
        float acc = r1b2[tid];
        #pragma unroll 8
        for (int k = 0; k < HH; k++) acc += __ldg(&r1w2[tid * HH + k]) * t[k];
        float pr = r1bp[tid];
        #pragma unroll 8
        for (int k = 0; k < D0; k++) pr += __ldg(&r1wp[tid * D0 + k]) * z[k];
        h[tid] = acc + pr;
    }
    __syncthreads();

    // LayerNorm over H=256 (block reduce), result in a[]
    auto ln256 = [&](const float* g, const float* bt) {
        float val = h[tid];
        float s = bred(val, red);
        float m = s * (1.0f / (float)HH);
        float d = val - m;
        float vv = bred(d * d, red) * (1.0f / (float)HH);
        float rs = 1.0f / sqrtf(vv + 1e-5f);
        a[tid] = d * rs * g[tid] + bt[tid];
        __syncthreads();
    };

    // ---- residual block 2 (H -> H) ----
    ln256(r2lg, r2lb);
    {
        float acc = r2b1[tid];
        #pragma unroll 8
        for (int k = 0; k < HH; k++) acc += __ldg(&r2w1[tid * HH + k]) * a[k];
        t[tid] = geluf(acc);
    }
    __syncthreads();
    {
        float acc = r2b2[tid];
        #pragma unroll 8
        for (int k = 0; k < HH; k++) acc += __ldg(&r2w2[tid * HH + k]) * t[k];
        h[tid] += acc;
    }
    __syncthreads();

    // ---- attention: all tokens identical -> softmax uniform -> o == v ----
    ln256(alg, alb);
    {   // v = att_win rows [2H, 3H) @ a + bin[2H:]
        float acc = abin[2 * HH + tid];
        #pragma unroll 8
        for (int k = 0; k < HH; k++) acc += __ldg(&awin[(2 * HH + tid) * HH + k]) * a[k];
        t[tid] = acc;
    }
    __syncthreads();
    {   // out_proj
        float acc = about_[tid];
        #pragma unroll 8
        for (int k = 0; k < HH; k++) acc += __ldg(&awout[tid * HH + k]) * t[k];
        a[tid] = acc;
    }
    __syncthreads();
    {   // final output linear
        float acc = ob[tid];
        #pragma unroll 8
        for (int k = 0; k < HH; k++) acc += __ldg(&ow[tid * HH + k]) * a[k];
        h[tid] = acc;
    }
    __syncthreads();

    // logits: l_j = (fin_w[j,:H] + fin_w[j,H:]) . h + fin_b[j]
    float p0 = (__ldg(&fw[tid])            + __ldg(&fw[HH + tid]))            * h[tid];
    float p1 = (__ldg(&fw[2 * HH + tid])   + __ldg(&fw[3 * HH + tid]))        * h[tid];
    float l0 = bred(p0, red) + fb[0];
    float l1 = bred(p1, red) + fb[1];
    if (tid == 0) g_c[b] = expf(l1 - l0);
}

// Fill symmetric adjacency. One block per 32x32 upper-triangular tile per batch.
// e(i<j) = 1 iff l0+g0 >= l1+g1  <=>  w1 >= c*w0,  w = -log(u+1e-10)+1e-10.
__global__ void __launch_bounds__(256) fill_adj_kernel(const float2* __restrict__ u2,
                                                       float* __restrict__ out) {
    const int b = blockIdx.y;
    const int tlin = blockIdx.x;                  // 0..527
    // decode (r, c), r <= c, among 32x32 tiles: tlin = r*(65-r)/2 + (c-r)
    int r = (int)((65.0f - sqrtf(4225.0f - 8.0f * (float)tlin)) * 0.5f);
    while (r > 0 && r * (65 - r) / 2 > tlin) r--;
    while ((r + 1) * (65 - (r + 1)) / 2 <= tlin) r++;
    const int c = r + (tlin - r * (65 - r) / 2);
    const int i0 = r << 5, j0 = c << 5;

    const float cb = g_c[b];
    const float2* __restrict__ ub = u2 + (size_t)b * PP;
    __shared__ float tile[32][33];

    const int tx = threadIdx.x;
    const size_t base = (size_t)b * NN * NN;

    if (i0 != j0) {
        #pragma unroll
        for (int rr = 0; rr < 4; rr++) {
            const int ti = threadIdx.y + (rr << 3);
            const int i = i0 + ti, j = j0 + tx;
            const int p = (i * (2047 - i)) / 2 + (j - i - 1);
            const float2 uu = __ldg(&ub[p]);
            const float w0 = 1e-10f - logf(uu.x + 1e-10f);
            const float w1 = 1e-10f - logf(uu.y + 1e-10f);
            tile[ti][tx] = (w1 >= cb * w0) ? 1.0f : 0.0f;
        }
        __syncthreads();
        #pragma unroll
        for (int rr = 0; rr < 4; rr++) {
            const int ti = threadIdx.y + (rr << 3);
            out[base + (size_t)(i0 + ti) * NN + j0 + tx] = tile[ti][tx];   // upper
            out[base + (size_t)(j0 + ti) * NN + i0 + tx] = tile[tx][ti];   // lower (transpose)
        }
    } else {
        #pragma unroll
        for (int rr = 0; rr < 4; rr++) {
            const int ti = threadIdx.y + (rr << 3);
            float e = 0.0f;
            if (tx > ti) {
                const int i = i0 + ti, j = j0 + tx;
                const int p = (i * (2047 - i)) / 2 + (j - i - 1);
                const float2 uu = __ldg(&ub[p]);
                const float w0 = 1e-10f - logf(uu.x + 1e-10f);
                const float w1 = 1e-10f - logf(uu.y + 1e-10f);
                e = (w1 >= cb * w0) ? 1.0f : 0.0f;
            }
            tile[ti][tx] = e;
        }
        __syncthreads();
        #pragma unroll
        for (int rr = 0; rr < 4; rr++) {
            const int ti = threadIdx.y + (rr << 3);
            const float v = (tx > ti) ? tile[ti][tx] : tile[tx][ti];  // tx==ti -> 0
            out[base + (size_t)(i0 + ti) * NN + j0 + tx] = v;
        }
    }
}

extern "C" void kernel_launch(void* const* d_in, const int* in_sizes, int n_in,
                              void* d_out, int out_size) {
    Ptrs P;
    for (int i = 0; i < 30; i++) P.p[i] = (const float*)d_in[i];

    logits_kernel<<<BB, 256>>>(P);

    dim3 grid(528, BB), blk(32, 8);
    fill_adj_kernel<<<grid, blk>>>((const float2*)d_in[2], (float*)d_out);
}

// round 2
// speedup vs baseline: 2.7623x; 2.7623x over previous
#include <cuda_runtime.h>
#include <math.h>

#define NN 1024
#define HH 256
#define D0 71
#define BB 16
#define PP 523776   // NN*(NN-1)/2

// per-batch decision constant c = exp(l1 - l0)
__device__ float g_c[BB];

struct Ptrs { const float* p[30]; };

__device__ __forceinline__ float bred(float v, float* red) {
    #pragma unroll
    for (int o = 16; o > 0; o >>= 1) v += __shfl_down_sync(0xffffffffu, v, o);
    int lane = threadIdx.x & 31, w = threadIdx.x >> 5;
    if (lane == 0) red[w] = v;
    __syncthreads();
    if (w == 0) {
        float s = (lane < 8) ? red[lane] : 0.0f;
        #pragma unroll
        for (int o = 4; o > 0; o >>= 1) s += __shfl_down_sync(0xffffffffu, s, o);
        if (lane == 0) red[0] = s;
    }
    __syncthreads();
    float s = red[0];
    __syncthreads();
    return s;
}

__device__ __forceinline__ float geluf(float x) {
    return 0.5f * x * (1.0f + erff(x * 0.70710678118654752440f));
}

// Warp-coalesced GEMV, 256x256 weight. Each warp computes the 32 rows
// matching its threads; lanes read consecutive float4s (coalesced LDG.128),
// partials go to a conflict-free shared array, thread tid reduces its row.
__device__ __forceinline__ float gemv256_acc(const float* __restrict__ w,
                                             const float* __restrict__ avec,
                                             float* __restrict__ part) {
    const int tid = threadIdx.x, lane = tid & 31, wp = tid >> 5;
    __syncwarp();   // protect part[] from previous use by this warp
    const float4* w4 = (const float4*)w;
    const float4* av = (const float4*)avec;
    const float4 a0 = av[lane];
    const float4 a1 = av[32 + lane];
    const int rbase = wp << 5;
    #pragma unroll
    for (int g = 0; g < 8; g++) {
        #pragma unroll
        for (int rr = 0; rr < 4; rr++) {
            const int r = rbase + (g << 2) + rr;
            const float4 x0 = __ldg(&w4[r * 64 + lane]);
            const float4 x1 = __ldg(&w4[r * 64 + 32 + lane]);
            float s = fmaf(x0.x, a0.x, x0.y * a0.y);
            s = fmaf(x0.z, a0.z, s); s = fmaf(x0.w, a0.w, s);
            s = fmaf(x1.x, a1.x, s); s = fmaf(x1.y, a1.y, s);
            s = fmaf(x1.z, a1.z, s); s = fmaf(x1.w, a1.w, s);
            part[r * 33 + lane] = s;
        }
    }
    __syncwarp();
    float acc = 0.f;
    #pragma unroll
    for (int i = 0; i < 32; i++) acc += part[tid * 33 + i];
    return acc;
}

// Same idea for the D0=71 input GEMVs.
__device__ __forceinline__ float gemv71_acc(const float* __restrict__ w,
                                            const float* __restrict__ avec,
                                            float* __restrict__ part) {
    const int tid = threadIdx.x, lane = tid & 31, wp = tid >> 5;
    __syncwarp();
    const float a0 = avec[lane];
    const float a1 = avec[lane + 32];
    const float a2 = (lane + 64 < D0) ? avec[lane + 64] : 0.f;
    const int rbase = wp << 5;
    #pragma unroll
    for (int g = 0; g < 32; g++) {
        const int r = rbase + g;
        const float* wr = w + r * D0;
        float s = __ldg(&wr[lane]) * a0 + __ldg(&wr[lane + 32]) * a1;
        if (lane + 64 < D0) s += __ldg(&wr[lane + 64]) * a2;
        part[r * 33 + lane] = s;
    }
    __syncwarp();
    float acc = 0.f;
    #pragma unroll
    for (int i = 0; i < 32; i++) acc += part[tid * 33 + i];
    return acc;
}

// One block per batch, 256 threads. Computes g_c[b] = exp(l1 - l0).
__global__ void __launch_bounds__(256) logits_kernel(Ptrs P) {
    const float* x     = P.p[0];
    const float* stats = P.p[1];
    const float* ln0_g = P.p[3];  const float* ln0_b = P.p[4];
    const float* r1lg  = P.p[5];  const float* r1lb  = P.p[6];
    const float* r1w1  = P.p[7];  const float* r1b1  = P.p[8];
    const float* r1w2  = P.p[9];  const float* r1b2  = P.p[10];
    const float* r1wp  = P.p[11]; const float* r1bp  = P.p[12];
    const float* r2lg  = P.p[13]; const float* r2lb  = P.p[14];
    const float* r2w1  = P.p[15]; const float* r2b1  = P.p[16];
    const float* r2w2  = P.p[17]; const float* r2b2  = P.p[18];
    const float* alg   = P.p[19]; const float* alb   = P.p[20];
    const float* awin  = P.p[21]; const float* abin  = P.p[22];
    const float* awout = P.p[23]; const float* about_= P.p[24];
    const float* ow    = P.p[25]; const float* ob    = P.p[26];
    const float* fw    = P.p[27]; const float* fb    = P.p[28];

    int b = blockIdx.x, tid = threadIdx.x;
    __shared__ __align__(16) float z[HH];   // padded; only D0 used
    __shared__ __align__(16) float a[HH];
    __shared__ __align__(16) float t[HH];
    __shared__ __align__(16) float h[HH];
    __shared__ float part[HH * 33];
    __shared__ float red[32], mv[2];

    // zero-pad z so float4 shared reads are safe
    z[tid < HH ? tid : 0] = 0.f;
    __syncthreads();
    if (tid < 64)       z[tid] = x[b * 64 + tid];
    else if (tid < D0)  z[tid] = stats[b * 7 + tid - 64];
    __syncthreads();

    // ln0 over 71 dims (serial stats on thread 0 — negligible)
    if (tid == 0) {
        float s = 0.f; for (int k = 0; k < D0; k++) s += z[k];
        float m = s / (float)D0, vv = 0.f;
        for (int k = 0; k < D0; k++) { float d = z[k] - m; vv += d * d; }
        vv /= (float)D0;
        mv[0] = m; mv[1] = 1.0f / sqrtf(vv + 1e-5f);
    }
    __syncthreads();
    if (tid < D0) z[tid] = (z[tid] - mv[0]) * mv[1] * ln0_g[tid] + ln0_b[tid];
    __syncthreads();

    // ---- residual block 1 (D0 -> H, with projection) ----
    if (tid == 0) {
        float s = 0.f; for (int k = 0; k < D0; k++) s += z[k];
        float m = s / (float)D0, vv = 0.f;
        for (int k = 0; k < D0; k++) { float d = z[k] - m; vv += d * d; }
        vv /= (float)D0;
        mv[0] = m; mv[1] = 1.0f / sqrtf(vv + 1e-5f);
    }
    __syncthreads();
    a[tid] = 0.f;
    __syncthreads();
    if (tid < D0) a[tid] = (z[tid] - mv[0]) * mv[1] * r1lg[tid] + r1lb[tid];
    __syncthreads();

    t[tid] = geluf(gemv71_acc(r1w1, a, part) + __ldg(&r1b1[tid]));
    __syncthreads();

    h[tid] = gemv256_acc(r1w2, t, part) + __ldg(&r1b2[tid])
           + gemv71_acc(r1wp, z, part) + __ldg(&r1bp[tid]);
    __syncthreads();

    // LayerNorm over H=256 (block reduce), result in a[]
    auto ln256 = [&](const float* g, const float* bt) {
        float val = h[tid];
        float s = bred(val, red);
        float m = s * (1.0f / (float)HH);
        float d = val - m;
        float vv = bred(d * d, red) * (1.0f / (float)HH);
        float rs = 1.0f / sqrtf(vv + 1e-5f);
        a[tid] = d * rs * g[tid] + bt[tid];
        __syncthreads();
    };

    // ---- residual block 2 (H -> H) ----
    ln256(r2lg, r2lb);
    t[tid] = geluf(gemv256_acc(r2w1, a, part) + __ldg(&r2b1[tid]));
    __syncthreads();
    h[tid] += gemv256_acc(r2w2, t, part) + __ldg(&r2b2[tid]);
    __syncthreads();

    // ---- attention: all tokens identical -> softmax uniform -> o == v ----
    ln256(alg, alb);
    t[tid] = gemv256_acc(awin + 2 * HH * HH, a, part) + __ldg(&abin[2 * HH + tid]);
    __syncthreads();
    a[tid] = gemv256_acc(awout, t, part) + __ldg(&about_[tid]);
    __syncthreads();
    h[tid] = gemv256_acc(ow, a, part) + __ldg(&ob[tid]);
    __syncthreads();

    // logits: l_j = (fin_w[j,:H] + fin_w[j,H:]) . h + fin_b[j]
    float p0 = (__ldg(&fw[tid])          + __ldg(&fw[HH + tid]))     * h[tid];
    float p1 = (__ldg(&fw[2 * HH + tid]) + __ldg(&fw[3 * HH + tid])) * h[tid];
    float l0 = bred(p0, red) + fb[0];
    float l1 = bred(p1, red) + fb[1];
    if (tid == 0) g_c[b] = expf(l1 - l0);
}

// decision: e(i<j) = 1 iff w1 >= c*w0,  w = -log(u+1e-10)+1e-10.
// Fast MUFU log with exact-log fallback inside the error margin.
__device__ __forceinline__ float edge_val(float ux, float uy, float cb) {
    const float w0 = 1e-10f - __logf(ux + 1e-10f);
    const float w1 = 1e-10f - __logf(uy + 1e-10f);
    const float cw0 = cb * w0;
    const float d = w1 - cw0;
    const float margin = 3e-6f * (fabsf(w1) + fabsf(cw0)) + 2e-7f;
    if (fabsf(d) > margin) return d >= 0.f ? 1.0f : 0.0f;
    const float e0 = 1e-10f - logf(ux + 1e-10f);
    const float e1 = 1e-10f - logf(uy + 1e-10f);
    return (e1 >= cb * e0) ? 1.0f : 0.0f;
}

// Fill symmetric adjacency. One block per 32x32 upper-triangular tile per batch.
__global__ void __launch_bounds__(256) fill_adj_kernel(const float2* __restrict__ u2,
                                                       float* __restrict__ out) {
    const int b = blockIdx.y;
    const int tlin = blockIdx.x;                  // 0..527
    int r = (int)((65.0f - sqrtf(4225.0f - 8.0f * (float)tlin)) * 0.5f);
    while (r > 0 && r * (65 - r) / 2 > tlin) r--;
    while ((r + 1) * (65 - (r + 1)) / 2 <= tlin) r++;
    const int c = r + (tlin - r * (65 - r) / 2);
    const int i0 = r << 5, j0 = c << 5;

    const float cb = g_c[b];
    const float2* __restrict__ ub = u2 + (size_t)b * PP;
    __shared__ float tile[32][33];

    const int tx = threadIdx.x;
    const size_t base = (size_t)b * NN * NN;

    if (i0 != j0) {
        #pragma unroll
        for (int rr = 0; rr < 4; rr++) {
            const int ti = threadIdx.y + (rr << 3);
            const int i = i0 + ti, j = j0 + tx;
            const int p = (i * (2047 - i)) / 2 + (j - i - 1);
            const float2 uu = __ldg(&ub[p]);
            tile[ti][tx] = edge_val(uu.x, uu.y, cb);
        }
        __syncthreads();
        #pragma unroll
        for (int rr = 0; rr < 4; rr++) {
            const int ti = threadIdx.y + (rr << 3);
            out[base + (size_t)(i0 + ti) * NN + j0 + tx] = tile[ti][tx];   // upper
            out[base + (size_t)(j0 + ti) * NN + i0 + tx] = tile[tx][ti];   // lower (transpose)
        }
    } else {
        #pragma unroll
        for (int rr = 0; rr < 4; rr++) {
            const int ti = threadIdx.y + (rr << 3);
            float e = 0.0f;
            if (tx > ti) {
                const int i = i0 + ti, j = j0 + tx;
                const int p = (i * (2047 - i)) / 2 + (j - i - 1);
                const float2 uu = __ldg(&ub[p]);
                e = edge_val(uu.x, uu.y, cb);
            }
            tile[ti][tx] = e;
        }
        __syncthreads();
        #pragma unroll
        for (int rr = 0; rr < 4; rr++) {
            const int ti = threadIdx.y + (rr << 3);
            const float v = (tx > ti) ? tile[ti][tx] : tile[tx][ti];  // tx==ti -> 0
            out[base + (size_t)(i0 + ti) * NN + j0 + tx] = v;
        }
    }
}

extern "C" void kernel_launch(void* const* d_in, const int* in_sizes, int n_in,
                              void* d_out, int out_size) {
    Ptrs P;
    for (int i = 0; i < 30; i++) P.p[i] = (const float*)d_in[i];

    logits_kernel<<<BB, 256>>>(P);

    dim3 grid(528, BB), blk(32, 8);
    fill_adj_kernel<<<grid, blk>>>((const float2*)d_in[2], (float*)d_out);
}

// round 3
// speedup vs baseline: 3.7309x; 1.3507x over previous
#include <cuda_runtime.h>
#include <math.h>

#define NN 1024
#define HH 256
#define D0 71
#define BB 16
#define PP 523776   // NN*(NN-1)/2

__device__ float g_c[BB];
__device__ __align__(16) float g_z[BB][128];   // ln0 output, zero-padded past 71
__device__ __align__(16) float g_b1[BB][HH];
__device__ __align__(16) float g_b2[BB][HH];
__device__ __align__(16) float g_h[BB][HH];

struct Ptrs { const float* p[30]; };

__device__ __forceinline__ float bred(float v, float* red) {
    #pragma unroll
    for (int o = 16; o > 0; o >>= 1) v += __shfl_down_sync(0xffffffffu, v, o);
    int lane = threadIdx.x & 31, w = threadIdx.x >> 5;
    if (lane == 0) red[w] = v;
    __syncthreads();
    if (w == 0) {
        float s = (lane < 8) ? red[lane] : 0.0f;
        #pragma unroll
        for (int o = 4; o > 0; o >>= 1) s += __shfl_down_sync(0xffffffffu, s, o);
        if (lane == 0) red[0] = s;
    }
    __syncthreads();
    float s = red[0];
    __syncthreads();
    return s;
}

__device__ __forceinline__ float geluf(float x) {
    return 0.5f * x * (1.0f + erff(x * 0.70710678118654752440f));
}

// Full-row dot of a 256-col weight row with activation held as two float4s per lane.
// Returns the complete dot on all lanes (xor-reduce).
__device__ __forceinline__ float dot256(const float* __restrict__ w, int row,
                                        float4 a0, float4 a1, int lane) {
    const float4* w4 = (const float4*)w + (size_t)row * 64;
    const float4 x0 = __ldg(&w4[lane]);
    const float4 x1 = __ldg(&w4[lane + 32]);
    float s = x0.x * a0.x + x0.y * a0.y + x0.z * a0.z + x0.w * a0.w
            + x1.x * a1.x + x1.y * a1.y + x1.z * a1.z + x1.w * a1.w;
    #pragma unroll
    for (int o = 16; o; o >>= 1) s += __shfl_xor_sync(0xffffffffu, s, o);
    return s;
}

// LayerNorm over 256 into shared sa[] (all 256 threads participate).
__device__ __forceinline__ void ln_block(const float* __restrict__ hv,
                                         const float* __restrict__ g,
                                         const float* __restrict__ bt,
                                         float* sa, float* red) {
    const int tid = threadIdx.x;
    const float v = hv[tid];
    const float s = bred(v, red);
    const float m = s * (1.0f / (float)HH);
    const float d = v - m;
    const float vv = bred(d * d, red) * (1.0f / (float)HH);
    const float rs = 1.0f / sqrtf(vv + 1e-5f);
    sa[tid] = d * rs * g[tid] + bt[tid];
    __syncthreads();
}

// ---------- K0: per-batch prologue (z, ln0, ln_rb1, t = gelu(r1w1 @ a)) ----------
__device__ __forceinline__ float gemv71_acc(const float* __restrict__ w,
                                            const float* __restrict__ avec,
                                            float* __restrict__ part) {
    const int tid = threadIdx.x, lane = tid & 31, wp = tid >> 5;
    __syncwarp();
    const float a0 = avec[lane];
    const float a1 = avec[lane + 32];
    const float a2 = (lane + 64 < D0) ? avec[lane + 64] : 0.f;
    const int rbase = wp << 5;
    #pragma unroll
    for (int g = 0; g < 32; g++) {
        const int r = rbase + g;
        const float* wr = w + r * D0;
        float s = __ldg(&wr[lane]) * a0 + __ldg(&wr[lane + 32]) * a1;
        if (lane + 64 < D0) s += __ldg(&wr[lane + 64]) * a2;
        part[r * 33 + lane] = s;
    }
    __syncwarp();
    float acc = 0.f;
    #pragma unroll
    for (int i = 0; i < 32; i++) acc += part[tid * 33 + i];
    return acc;
}

__global__ void __launch_bounds__(256) k0_prologue(Ptrs P) {
    const float* x = P.p[0]; const float* stats = P.p[1];
    const float* ln0_g = P.p[3]; const float* ln0_b = P.p[4];
    const float* r1lg = P.p[5];  const float* r1lb = P.p[6];
    const float* r1w1 = P.p[7];  const float* r1b1 = P.p[8];
    const int b = blockIdx.x, tid = threadIdx.x;
    __shared__ float z[128], a[128], mv[2];
    __shared__ float part[HH * 33];

    if (tid < 128) { z[tid] = 0.f; a[tid] = 0.f; }
    __syncthreads();
    if (tid < 64)      z[tid] = x[b * 64 + tid];
    else if (tid < D0) z[tid] = stats[b * 7 + tid - 64];
    __syncthreads();

    if (tid == 0) {
        float s = 0.f; for (int k = 0; k < D0; k++) s += z[k];
        float m = s / (float)D0, vv = 0.f;
        for (int k = 0; k < D0; k++) { float d = z[k] - m; vv += d * d; }
        vv /= (float)D0;
        mv[0] = m; mv[1] = 1.0f / sqrtf(vv + 1e-5f);
    }
    __syncthreads();
    if (tid < D0) z[tid] = (z[tid] - mv[0]) * mv[1] * ln0_g[tid] + ln0_b[tid];
    __syncthreads();

    if (tid == 0) {
        float s = 0.f; for (int k = 0; k < D0; k++) s += z[k];
        float m = s / (float)D0, vv = 0.f;
        for (int k = 0; k < D0; k++) { float d = z[k] - m; vv += d * d; }
        vv /= (float)D0;
        mv[0] = m; mv[1] = 1.0f / sqrtf(vv + 1e-5f);
    }
    __syncthreads();
    if (tid < D0) a[tid] = (z[tid] - mv[0]) * mv[1] * r1lg[tid] + r1lb[tid];
    __syncthreads();

    g_b1[b][tid] = geluf(gemv71_acc(r1w1, a, part) + __ldg(&r1b1[tid]));
    if (tid < 128) g_z[b][tid] = z[tid];   // zero-padded
}

// ---------- K1: h = r1w2 @ t + r1wp @ z' + b2 + bp (32 rows/block) ----------
__global__ void __launch_bounds__(256) k1_rb1(Ptrs P) {
    const float* r1w2 = P.p[9];  const float* r1b2 = P.p[10];
    const float* r1wp = P.p[11]; const float* r1bp = P.p[12];
    const int b = blockIdx.y, rb = blockIdx.x << 5;
    const int tid = threadIdx.x, lane = tid & 31, wp = tid >> 5;
    const float4* t4 = (const float4*)g_b1[b];
    const float4 a0 = __ldg(&t4[lane]);
    const float4 a1 = __ldg(&t4[lane + 32]);
    const float z0 = g_z[b][lane], z1 = g_z[b][lane + 32];
    const float z2 = (lane < 7) ? g_z[b][lane + 64] : 0.f;
    #pragma unroll
    for (int r = 0; r < 4; r++) {
        const int row = rb + (wp << 2) + r;
        const float* wr = r1wp + row * D0;
        float sp = __ldg(&wr[lane]) * z0 + __ldg(&wr[lane + 32]) * z1;
        if (lane < 7) sp += __ldg(&wr[lane + 64]) * z2;
        const float4* w4 = (const float4*)r1w2 + (size_t)row * 64;
        const float4 x0 = __ldg(&w4[lane]);
        const float4 x1 = __ldg(&w4[lane + 32]);
        float s = x0.x * a0.x + x0.y * a0.y + x0.z * a0.z + x0.w * a0.w
                + x1.x * a1.x + x1.y * a1.y + x1.z * a1.z + x1.w * a1.w + sp;
        #pragma unroll
        for (int o = 16; o; o >>= 1) s += __shfl_xor_sync(0xffffffffu, s, o);
        if (lane == 0) g_h[b][row] = s + __ldg(&r1b2[row]) + __ldg(&r1bp[row]);
    }
}

// ---------- K2: t = gelu(r2w1 @ LN(h)) ----------
__global__ void __launch_bounds__(256) k2_rb2a(Ptrs P) {
    const float* r2lg = P.p[13]; const float* r2lb = P.p[14];
    const float* r2w1 = P.p[15]; const float* r2b1 = P.p[16];
    const int b = blockIdx.y, rb = blockIdx.x << 5;
    const int tid = threadIdx.x, lane = tid & 31, wp = tid >> 5;
    __shared__ __align__(16) float sa[HH];
    __shared__ float red[32];
    ln_block(g_h[b], r2lg, r2lb, sa, red);
    const float4* sa4 = (const float4*)sa;
    const float4 a0 = sa4[lane], a1 = sa4[lane + 32];
    #pragma unroll
    for (int r = 0; r < 4; r++) {
        const int row = rb + (wp << 2) + r;
        const float s = dot256(r2w1, row, a0, a1, lane);
        if (lane == 0) g_b1[b][row] = geluf(s + __ldg(&r2b1[row]));
    }
}

// ---------- K3: h += r2w2 @ t + b2 ----------
__global__ void __launch_bounds__(256) k3_rb2b(Ptrs P) {
    const float* r2w2 = P.p[17]; const float* r2b2 = P.p[18];
    const int b = blockIdx.y, rb = blockIdx.x << 5;
    const int tid = threadIdx.x, lane = tid & 31, wp = tid >> 5;
    const float4* t4 = (const float4*)g_b1[b];
    const float4 a0 = __ldg(&t4[lane]), a1 = __ldg(&t4[lane + 32]);
    #pragma unroll
    for (int r = 0; r < 4; r++) {
        const int row = rb + (wp << 2) + r;
        const float s = dot256(r2w2, row, a0, a1, lane);
        if (lane == 0) g_h[b][row] += s + __ldg(&r2b2[row]);
    }
}

// ---------- K4: t = awin_v @ LN(h) + bin_v ----------
__global__ void __launch_bounds__(256) k4_attv(Ptrs P) {
    const float* alg = P.p[19]; const float* alb = P.p[20];
    const float* awin = P.p[21]; const float* abin = P.p[22];
    const int b = blockIdx.y, rb = blockIdx.x << 5;
    const int tid = threadIdx.x, lane = tid & 31, wp = tid >> 5;
    __shared__ __align__(16) float sa[HH];
    __shared__ float red[32];
    ln_block(g_h[b], alg, alb, sa, red);
    const float4* sa4 = (const float4*)sa;
    const float4 a0 = sa4[lane], a1 = sa4[lane + 32];
    const float* wv = awin + 2 * HH * HH;
    #pragma unroll
    for (int r = 0; r < 4; r++) {
        const int row = rb + (wp << 2) + r;
        const float s = dot256(wv, row, a0, a1, lane);
        if (lane == 0) g_b1[b][row] = s + __ldg(&abin[2 * HH + row]);
    }
}

// ---------- K5: a = awout @ t + bout ----------
__global__ void __launch_bounds__(256) k5_attout(Ptrs P) {
    const float* awout = P.p[23]; const float* about_ = P.p[24];
    const int b = blockIdx.y, rb = blockIdx.x << 5;
    const int tid = threadIdx.x, lane = tid & 31, wp = tid >> 5;
    const float4* t4 = (const float4*)g_b1[b];
    const float4 a0 = __ldg(&t4[lane]), a1 = __ldg(&t4[lane + 32]);
    #pragma unroll
    for (int r = 0; r < 4; r++) {
        const int row = rb + (wp << 2) + r;
        const float s = dot256(awout, row, a0, a1, lane);
        if (lane == 0) g_b2[b][row] = s + __ldg(&about_[row]);
    }
}

// ---------- K6: h2 = ow @ a + ob ----------
__global__ void __launch_bounds__(256) k6_out(Ptrs P) {
    const float* ow = P.p[25]; const float* ob = P.p[26];
    const int b = blockIdx.y, rb = blockIdx.x << 5;
    const int tid = threadIdx.x, lane = tid & 31, wp = tid >> 5;
    const float4* t4 = (const float4*)g_b2[b];
    const float4 a0 = __ldg(&t4[lane]), a1 = __ldg(&t4[lane + 32]);
    #pragma unroll
    for (int r = 0; r < 4; r++) {
        const int row = rb + (wp << 2) + r;
        const float s = dot256(ow, row, a0, a1, lane);
        if (lane == 0) g_b1[b][row] = s + __ldg(&ob[row]);
    }
}

// ---------- K7: g_c[b] = exp(l1 - l0) ----------
__global__ void __launch_bounds__(256) k7_final(Ptrs P) {
    const float* fw = P.p[27]; const float* fb = P.p[28];
    const int b = blockIdx.x, tid = threadIdx.x;
    __shared__ float red[32];
    const float hv = g_b1[b][tid];
    const float p0 = (__ldg(&fw[tid])          + __ldg(&fw[HH + tid]))     * hv;
    const float p1 = (__ldg(&fw[2 * HH + tid]) + __ldg(&fw[3 * HH + tid])) * hv;
    const float l0 = bred(p0, red) + fb[0];
    const float l1 = bred(p1, red) + fb[1];
    if (tid == 0) g_c[b] = expf(l1 - l0);
}

// ---------- fill: e(i<j) = 1 iff w1 >= c*w0, w = -log(u+1e-10)+1e-10 ----------
__device__ __forceinline__ float edge_val(float ux, float uy, float cb) {
    const float w0 = 1e-10f - __logf(ux + 1e-10f);
    const float w1 = 1e-10f - __logf(uy + 1e-10f);
    const float cw0 = cb * w0;
    const float d = w1 - cw0;
    const float margin = 3e-6f * (fabsf(w1) + fabsf(cw0)) + 2e-7f;
    if (fabsf(d) > margin) return d >= 0.f ? 1.0f : 0.0f;
    const float e0 = 1e-10f - logf(ux + 1e-10f);
    const float e1 = 1e-10f - logf(uy + 1e-10f);
    return (e1 >= cb * e0) ? 1.0f : 0.0f;
}

// 64x64 tiles, 2 edges/thread, direct upper write, shared transpose for lower.
__global__ void __launch_bounds__(256) fill_adj_kernel(const float2* __restrict__ u2,
                                                       float* __restrict__ out) {
    const int b = blockIdx.y;
    const int tl = blockIdx.x;                   // 0..135
    int r = (int)((33.0f - sqrtf(1089.0f - 8.0f * (float)tl)) * 0.5f);
    while (r > 0 && r * (33 - r) / 2 > tl) r--;
    while ((r + 1) * (33 - (r + 1)) / 2 <= tl) r++;
    const int c = r + (tl - r * (33 - r) / 2);
    const int i0 = r << 6, j0 = c << 6;

    const float cb = g_c[b];
    const float2* __restrict__ ub = u2 + (size_t)b * PP;
    float* __restrict__ ob = out + (size_t)b * NN * NN;
    __shared__ float tile[64][66];

    const int tx = threadIdx.x, ty = threadIdx.y;

    if (i0 != j0) {
        #pragma unroll
        for (int rr = 0; rr < 8; rr++) {
            const int ti = ty + (rr << 3);
            const int i = i0 + ti;
            const int pb = (i * (2047 - i)) / 2 - i - 1 + j0 + 2 * tx;
            const float2 ua = __ldg(&ub[pb]);
            const float2 uc = __ldg(&ub[pb + 1]);
            const float e0 = edge_val(ua.x, ua.y, cb);
            const float e1 = edge_val(uc.x, uc.y, cb);
            *(float2*)&ob[(size_t)i * NN + j0 + 2 * tx] = make_float2(e0, e1);
            *(float2*)&tile[ti][2 * tx] = make_float2(e0, e1);
        }
        __syncthreads();
        #pragma unroll
        for (int rr = 0; rr < 8; rr++) {
            const int tj = ty + (rr << 3);
            const float f0 = tile[2 * tx][tj];
            const float f1 = tile[2 * tx + 1][tj];
            *(float2*)&ob[(size_t)(j0 + tj) * NN + i0 + 2 * tx] = make_float2(f0, f1);
        }
    } else {
        #pragma unroll
        for (int rr = 0; rr < 8; rr++) {
            const int ti = ty + (rr << 3);
            const int i = i0 + ti;
            const int pbase = (i * (2047 - i)) / 2 - i - 1 + j0;
            float e0 = 0.f, e1 = 0.f;
            if (2 * tx > ti) {
                const float2 ua = __ldg(&ub[pbase + 2 * tx]);
                e0 = edge_val(ua.x, ua.y, cb);
            }
            if (2 * tx + 1 > ti) {
                const float2 uc = __ldg(&ub[pbase + 2 * tx + 1]);
                e1 = edge_val(uc.x, uc.y, cb);
            }
            *(float2*)&tile[ti][2 * tx] = make_float2(e0, e1);
            // upper (incl. diagonal zeros): write col s when s >= ti
            if (2 * tx >= ti)     ob[(size_t)i * NN + j0 + 2 * tx] = e0;
            if (2 * tx + 1 >= ti) ob[(size_t)i * NN + j0 + 2 * tx + 1] = e1;
        }
        __syncthreads();
        #pragma unroll
        for (int rr = 0; rr < 8; rr++) {
            const int tj = ty + (rr << 3);
            // lower strictly below diagonal: col s < tj
            if (2 * tx < tj)     ob[(size_t)(j0 + tj) * NN + i0 + 2 * tx]     = tile[2 * tx][tj];
            if (2 * tx + 1 < tj) ob[(size_t)(j0 + tj) * NN + i0 + 2 * tx + 1] = tile[2 * tx + 1][tj];
        }
    }
}

extern "C" void kernel_launch(void* const* d_in, const int* in_sizes, int n_in,
                              void* d_out, int out_size) {
    Ptrs P;
    for (int i = 0; i < 30; i++) P.p[i] = (const float*)d_in[i];

    dim3 gs(8, BB);
    k0_prologue<<<BB, 256>>>(P);
    k1_rb1   <<<gs, 256>>>(P);
    k2_rb2a  <<<gs, 256>>>(P);
    k3_rb2b  <<<gs, 256>>>(P);
    k4_attv  <<<gs, 256>>>(P);
    k5_attout<<<gs, 256>>>(P);
    k6_out   <<<gs, 256>>>(P);
    k7_final <<<BB, 256>>>(P);

    dim3 grid(136, BB), blk(32, 8);
    fill_adj_kernel<<<grid, blk>>>((const float2*)d_in[2], (float*)d_out);
}

// round 4
// speedup vs baseline: 4.0185x; 1.0771x over previous
#include <cuda_runtime.h>
#include <math.h>

#define NN 1024
#define HH 256
#define D0 71
#define BB 16
#define PP 523776   // NN*(NN-1)/2

__device__ float g_c[BB];

struct Ptrs { const float* p[30]; };

__device__ __forceinline__ float geluf(float x) {
    return 0.5f * x * (1.0f + erff(x * 0.70710678118654752440f));
}

// Block-wide sum over 1024 threads (32 warps).
__device__ __forceinline__ float bred32(float v, float* red) {
    #pragma unroll
    for (int o = 16; o > 0; o >>= 1) v += __shfl_down_sync(0xffffffffu, v, o);
    const int lane = threadIdx.x & 31, wp = threadIdx.x >> 5;
    if (lane == 0) red[wp] = v;
    __syncthreads();
    if (wp == 0) {
        float s = red[lane];
        #pragma unroll
        for (int o = 16; o > 0; o >>= 1) s += __shfl_down_sync(0xffffffffu, s, o);
        if (lane == 0) red[0] = s;
    }
    __syncthreads();
    const float s = red[0];
    __syncthreads();
    return s;
}

// LayerNorm over 256 values (block of 1024 threads), writes sa[0:256].
__device__ __forceinline__ void ln1024(const float* __restrict__ hv,
                                       const float* __restrict__ g,
                                       const float* __restrict__ bt,
                                       float* sa, float* red) {
    const int tid = threadIdx.x;
    const float v = (tid < HH) ? hv[tid] : 0.f;
    const float s = bred32(v, red);
    const float m = s * (1.0f / (float)HH);
    const float d = v - m;
    const float vv = bred32((tid < HH) ? d * d : 0.f, red) * (1.0f / (float)HH);
    const float rs = 1.0f / sqrtf(vv + 1e-5f);
    if (tid < HH) sa[tid] = d * rs * g[tid] + bt[tid];
    __syncthreads();
}

// One warp row-dot of a 256-wide weight row; full sum returned on all lanes.
__device__ __forceinline__ float wdot256(const float* __restrict__ w, int row,
                                         float4 a0, float4 a1, int lane) {
    const float4* w4 = (const float4*)w + (size_t)row * 64;
    const float4 x0 = __ldg(&w4[lane]);
    const float4 x1 = __ldg(&w4[lane + 32]);
    float s = x0.x * a0.x + x0.y * a0.y + x0.z * a0.z + x0.w * a0.w
            + x1.x * a1.x + x1.y * a1.y + x1.z * a1.z + x1.w * a1.w;
    #pragma unroll
    for (int o = 16; o; o >>= 1) s += __shfl_xor_sync(0xffffffffu, s, o);
    return s;
}

// Entire logits network in one kernel. 16 blocks x 1024 threads.
// Each warp owns 8 rows of every 256-row GEMV stage.
__global__ void __launch_bounds__(1024) logits_all(Ptrs P) {
    const float* x     = P.p[0];  const float* stats = P.p[1];
    const float* ln0_g = P.p[3];  const float* ln0_b = P.p[4];
    const float* r1lg  = P.p[5];  const float* r1lb  = P.p[6];
    const float* r1w1  = P.p[7];  const float* r1b1  = P.p[8];
    const float* r1w2  = P.p[9];  const float* r1b2  = P.p[10];
    const float* r1wp  = P.p[11]; const float* r1bp  = P.p[12];
    const float* r2lg  = P.p[13]; const float* r2lb  = P.p[14];
    const float* r2w1  = P.p[15]; const float* r2b1  = P.p[16];
    const float* r2w2  = P.p[17]; const float* r2b2  = P.p[18];
    const float* alg   = P.p[19]; const float* alb   = P.p[20];
    const float* awin  = P.p[21]; const float* abin  = P.p[22];
    const float* awout = P.p[23]; const float* about_= P.p[24];
    const float* ow    = P.p[25]; const float* ob    = P.p[26];
    const float* fw    = P.p[27]; const float* fb    = P.p[28];

    const int b = blockIdx.x, tid = threadIdx.x, lane = tid & 31, wp = tid >> 5;
    __shared__ __align__(16) float z[128], za[128];
    __shared__ __align__(16) float sa[HH], sb[HH], sh[HH], st[HH];
    __shared__ float red[32], mv[2];

    if (tid < 128) { z[tid] = 0.f; za[tid] = 0.f; }
    __syncthreads();
    if (tid < 64)      z[tid] = x[b * 64 + tid];
    else if (tid < D0) z[tid] = stats[b * 7 + tid - 64];
    __syncthreads();

    // ln0 (serial stats over 71 elems on thread 0 — negligible)
    if (tid == 0) {
        float s = 0.f; for (int k = 0; k < D0; k++) s += z[k];
        float m = s / (float)D0, vv = 0.f;
        for (int k = 0; k < D0; k++) { float d = z[k] - m; vv += d * d; }
        mv[0] = m; mv[1] = 1.0f / sqrtf(vv / (float)D0 + 1e-5f);
    }
    __syncthreads();
    if (tid < D0) z[tid] = (z[tid] - mv[0]) * mv[1] * ln0_g[tid] + ln0_b[tid];
    __syncthreads();
    // rb1 LN
    if (tid == 0) {
        float s = 0.f; for (int k = 0; k < D0; k++) s += z[k];
        float m = s / (float)D0, vv = 0.f;
        for (int k = 0; k < D0; k++) { float d = z[k] - m; vv += d * d; }
        mv[0] = m; mv[1] = 1.0f / sqrtf(vv / (float)D0 + 1e-5f);
    }
    __syncthreads();
    if (tid < D0) za[tid] = (z[tid] - mv[0]) * mv[1] * r1lg[tid] + r1lb[tid];
    __syncthreads();

    // Stage A: st = gelu(r1w1 @ za + b1)    [256 x 71]
    {
        const float a0 = za[lane], a1 = za[lane + 32], a2 = za[lane + 64]; // zero-padded
        #pragma unroll
        for (int r = 0; r < 8; r++) {
            const int row = (wp << 3) + r;
            const float* wr = r1w1 + row * D0;
            float s = __ldg(&wr[lane]) * a0 + __ldg(&wr[lane + 32]) * a1;
            if (lane < D0 - 64) s += __ldg(&wr[lane + 64]) * a2;
            #pragma unroll
            for (int o = 16; o; o >>= 1) s += __shfl_xor_sync(0xffffffffu, s, o);
            if (lane == 0) st[row] = geluf(s + __ldg(&r1b1[row]));
        }
    }
    __syncthreads();

    // Stage B: sh = r1w2 @ st + r1wp @ z + b2 + bp
    {
        const float4 a0 = ((const float4*)st)[lane];
        const float4 a1 = ((const float4*)st)[lane + 32];
        const float z0 = z[lane], z1 = z[lane + 32], z2 = z[lane + 64];
        #pragma unroll
        for (int r = 0; r < 8; r++) {
            const int row = (wp << 3) + r;
            const float* wr = r1wp + row * D0;
            float sp = __ldg(&wr[lane]) * z0 + __ldg(&wr[lane + 32]) * z1;
            if (lane < D0 - 64) sp += __ldg(&wr[lane + 64]) * z2;
            const float4* w4 = (const float4*)r1w2 + (size_t)row * 64;
            const float4 x0 = __ldg(&w4[lane]);
            const float4 x1 = __ldg(&w4[lane + 32]);
            float s = x0.x * a0.x + x0.y * a0.y + x0.z * a0.z + x0.w * a0.w
                    + x1.x * a1.x + x1.y * a1.y + x1.z * a1.z + x1.w * a1.w + sp;
            #pragma unroll
            for (int o = 16; o; o >>= 1) s += __shfl_xor_sync(0xffffffffu, s, o);
            if (lane == 0) sh[row] = s + __ldg(&r1b2[row]) + __ldg(&r1bp[row]);
        }
    }
    __syncthreads();

    // rb2: LN -> sa; st = gelu(r2w1 @ sa); sh += r2w2 @ st
    ln1024(sh, r2lg, r2lb, sa, red);
    {
        const float4 a0 = ((const float4*)sa)[lane];
        const float4 a1 = ((const float4*)sa)[lane + 32];
        #pragma unroll
        for (int r = 0; r < 8; r++) {
            const int row = (wp << 3) + r;
            const float s = wdot256(r2w1, row, a0, a1, lane);
            if (lane == 0) st[row] = geluf(s + __ldg(&r2b1[row]));
        }
    }
    __syncthreads();
    {
        const float4 a0 = ((const float4*)st)[lane];
        const float4 a1 = ((const float4*)st)[lane + 32];
        #pragma unroll
        for (int r = 0; r < 8; r++) {
            const int row = (wp << 3) + r;
            const float s = wdot256(r2w2, row, a0, a1, lane);
            if (lane == 0) sh[row] += s + __ldg(&r2b2[row]);
        }
    }
    __syncthreads();

    // attention (tokens identical -> o == v): LN -> v-proj -> out-proj -> final linear
    ln1024(sh, alg, alb, sa, red);
    {
        const float4 a0 = ((const float4*)sa)[lane];
        const float4 a1 = ((const float4*)sa)[lane + 32];
        const float* wv = awin + 2 * HH * HH;
        #pragma unroll
        for (int r = 0; r < 8; r++) {
            const int row = (wp << 3) + r;
            const float s = wdot256(wv, row, a0, a1, lane);
            if (lane == 0) st[row] = s + __ldg(&abin[2 * HH + row]);
        }
    }
    __syncthreads();
    {
        const float4 a0 = ((const float4*)st)[lane];
        const float4 a1 = ((const float4*)st)[lane + 32];
        #pragma unroll
        for (int r = 0; r < 8; r++) {
            const int row = (wp << 3) + r;
            const float s = wdot256(awout, row, a0, a1, lane);
            if (lane == 0) sb[row] = s + __ldg(&about_[row]);
        }
    }
    __syncthreads();
    {
        const float4 a0 = ((const float4*)sb)[lane];
        const float4 a1 = ((const float4*)sb)[lane + 32];
        #pragma unroll
        for (int r = 0; r < 8; r++) {
            const int row = (wp << 3) + r;
            const float s = wdot256(ow, row, a0, a1, lane);
            if (lane == 0) st[row] = s + __ldg(&ob[row]);
        }
    }
    __syncthreads();

    // logits: l_j = (fw[j,:H]+fw[j,H:]) . h + fb[j];  g_c = exp(l1-l0)
    const float hv = (tid < HH) ? st[tid] : 0.f;
    const float f0 = (tid < HH) ? __ldg(&fw[tid]) + __ldg(&fw[HH + tid]) : 0.f;
    const float f1 = (tid < HH) ? __ldg(&fw[2 * HH + tid]) + __ldg(&fw[3 * HH + tid]) : 0.f;
    const float l0 = bred32(f0 * hv, red) + fb[0];
    const float l1 = bred32(f1 * hv, red) + fb[1];
    if (tid == 0) g_c[b] = expf(l1 - l0);
}

// ---------- fill: e(i<j) = 1 iff w1 >= c*w0, w = -log(u+1e-10)+1e-10 ----------
__device__ __forceinline__ float edge_val(float ux, float uy, float cb) {
    const float w0 = 1e-10f - __logf(ux + 1e-10f);
    const float w1 = 1e-10f - __logf(uy + 1e-10f);
    const float cw0 = cb * w0;
    const float d = w1 - cw0;
    const float margin = 3e-6f * (fabsf(w1) + fabsf(cw0)) + 2e-7f;
    if (fabsf(d) > margin) return d >= 0.f ? 1.0f : 0.0f;
    const float e0 = 1e-10f - logf(ux + 1e-10f);
    const float e1 = 1e-10f - logf(uy + 1e-10f);
    return (e1 >= cb * e0) ? 1.0f : 0.0f;
}

// 64x64 tiles, 4 edges/thread, float4 stores both triangles.
__global__ void __launch_bounds__(256) fill_adj_kernel(const float2* __restrict__ u2,
                                                       float* __restrict__ out) {
    const int b = blockIdx.y;
    const int tl = blockIdx.x;                    // 0..135 (16x16 tile grid, upper tri)
    int r = (int)((33.0f - sqrtf(1089.0f - 8.0f * (float)tl)) * 0.5f);
    while (r > 0 && r * (33 - r) / 2 > tl) r--;
    while ((r + 1) * (33 - (r + 1)) / 2 <= tl) r++;
    const int c = r + (tl - r * (33 - r) / 2);
    const int i0 = r << 6, j0 = c << 6;

    const float cb = g_c[b];
    const float2* __restrict__ ub = u2 + (size_t)b * PP;
    float* __restrict__ obp = out + (size_t)b * NN * NN;
    __shared__ float tile[64][65];   // stored TRANSPOSED: tile[jloc][iloc]

    const int tx = threadIdx.x;      // 0..15 -> cols 4tx..4tx+3
    const int ty = threadIdx.y;      // 0..15

    if (i0 != j0) {
        #pragma unroll
        for (int rr = 0; rr < 4; rr++) {
            const int ti = ty + (rr << 4);
            const int i = i0 + ti;
            const int rowbase = (i * (2047 - i)) / 2 - i - 1 + j0;
            const int p0 = rowbase + 4 * tx;
            float4 ev;
            if (!(rowbase & 1)) {
                const float4* u4 = (const float4*)ub;
                const float4 A = __ldg(&u4[p0 >> 1]);
                const float4 Bq = __ldg(&u4[(p0 >> 1) + 1]);
                ev.x = edge_val(A.x,  A.y,  cb);
                ev.y = edge_val(A.z,  A.w,  cb);
                ev.z = edge_val(Bq.x, Bq.y, cb);
                ev.w = edge_val(Bq.z, Bq.w, cb);
            } else {
                const float2 a = __ldg(&ub[p0]);
                const float2 bq = __ldg(&ub[p0 + 1]);
                const float2 cq = __ldg(&ub[p0 + 2]);
                const float2 dq = __ldg(&ub[p0 + 3]);
                ev.x = edge_val(a.x,  a.y,  cb);
                ev.y = edge_val(bq.x, bq.y, cb);
                ev.z = edge_val(cq.x, cq.y, cb);
                ev.w = edge_val(dq.x, dq.y, cb);
            }
            *(float4*)&obp[(size_t)i * NN + j0 + 4 * tx] = ev;
            tile[4 * tx + 0][ti] = ev.x;
            tile[4 * tx + 1][ti] = ev.y;
            tile[4 * tx + 2][ti] = ev.z;
            tile[4 * tx + 3][ti] = ev.w;
        }
        __syncthreads();
        #pragma unroll
        for (int rr = 0; rr < 4; rr++) {
            const int tj = ty + (rr << 4);
            float4 f;
            f.x = tile[tj][4 * tx + 0];
            f.y = tile[tj][4 * tx + 1];
            f.z = tile[tj][4 * tx + 2];
            f.w = tile[tj][4 * tx + 3];
            *(float4*)&obp[(size_t)(j0 + tj) * NN + i0 + 4 * tx] = f;
        }
    } else {
        #pragma unroll
        for (int rr = 0; rr < 4; rr++) {
            const int ti = ty + (rr << 4);
            const int i = i0 + ti;
            const int rowbase = (i * (2047 - i)) / 2 - i - 1 + j0;
            #pragma unroll
            for (int k = 0; k < 4; k++) {
                const int col = 4 * tx + k;
                float e = 0.f;
                if (col > ti) {
                    const float2 uu = __ldg(&ub[rowbase + col]);
                    e = edge_val(uu.x, uu.y, cb);
                }
                tile[col][ti] = e;
                if (col >= ti) obp[(size_t)i * NN + j0 + col] = e;  // diag -> 0
            }
        }
        __syncthreads();
        #pragma unroll
        for (int rr = 0; rr < 4; rr++) {
            const int tj = ty + (rr << 4);
            #pragma unroll
            for (int k = 0; k < 4; k++) {
                const int col = 4 * tx + k;
                if (col < tj) obp[(size_t)(j0 + tj) * NN + i0 + col] = tile[tj][col];
            }
        }
    }
}

extern "C" void kernel_launch(void* const* d_in, const int* in_sizes, int n_in,
                              void* d_out, int out_size) {
    Ptrs P;
    for (int i = 0; i < 30; i++) P.p[i] = (const float*)d_in[i];

    logits_all<<<BB, 1024>>>(P);

    dim3 grid(136, BB), blk(16, 16);
    fill_adj_kernel<<<grid, blk>>>((const float2*)d_in[2], (float*)d_out);
}